// round 17
// baseline (speedup 1.0000x reference)
#include <cuda_runtime.h>
#include <math.h>
#include <stdint.h>

// Problem constants
#define BB 4
#define SS 2048
#define DD 1024
#define HH 16
#define HDIM 64
#define MTOT (BB * SS)                          // 8192
#define HEADTOT ((size_t)BB * HH * SS * HDIM)   // 8,388,608

// Scratch
__device__ float g_qh[BB * HH * SS * HDIM];
__device__ float g_att[BB * HH * SS * HDIM];    // RNA-pre-rounded by flash epilogue
__device__ float g_kt[BB * HH * SS * HDIM];     // K head-layout, RNA-rounded, d-permuted
__device__ float g_vt[BB * HH * HDIM * SS];     // V^T [b][h][d][s], RNA-rounded, s-permuted
__device__ float g_wr[4 * DD * DD];             // Wq,Wk,Wv,Wo RNA-pre-rounded

__device__ __forceinline__ uint32_t smem_u32(const void* p) {
    uint32_t a;
    asm("{ .reg .u64 t; cvta.to.shared.u64 t, %1; cvt.u32.u64 %0, t; }"
        : "=r"(a) : "l"(p));
    return a;
}

__device__ __forceinline__ uint32_t f2tf(float f) {
    uint32_t u;
    asm("cvt.rna.tf32.f32 %0, %1;" : "=r"(u) : "f"(f));
    return u;
}

__device__ __forceinline__ float rnd_tf(float f) {
    return __uint_as_float(f2tf(f));
}

// k-slot pairing permutation within 8-groups: p(j) = (j&3)*2 + (j>>2).
__device__ __forceinline__ int kperm(int j) { return ((j & 3) << 1) | (j >> 2); }

__device__ __forceinline__ void mma8(float* c, const uint32_t* a,
                                     uint32_t b0, uint32_t b1) {
    asm volatile(
        "mma.sync.aligned.m16n8k8.row.col.f32.tf32.tf32.f32 "
        "{%0,%1,%2,%3}, {%4,%5,%6,%7}, {%8,%9}, {%0,%1,%2,%3};"
        : "+f"(c[0]), "+f"(c[1]), "+f"(c[2]), "+f"(c[3])
        : "r"(a[0]), "r"(a[1]), "r"(a[2]), "r"(a[3]), "r"(b0), "r"(b1));
}

__device__ __forceinline__ void ldsm4(uint32_t& d0, uint32_t& d1,
                                      uint32_t& d2, uint32_t& d3, uint32_t addr) {
    asm volatile(
        "ldmatrix.sync.aligned.m8n8.x4.shared.b16 {%0,%1,%2,%3}, [%4];"
        : "=r"(d0), "=r"(d1), "=r"(d2), "=r"(d3) : "r"(addr));
}

// exp2(z) for z <= 0, FMA-pipe only (no MUFU). ~5e-5 rel err.
__device__ __forceinline__ float exp2p(float z) {
    z = fmaxf(z, -100.f);
    float k = z + 12582912.f;            // 1.5*2^23: round-to-nearest-int
    int nb = __float_as_int(k);
    float f = z - (k - 12582912.f);      // f in [-0.5, 0.5]
    float p = 0.00961813f;
    p = fmaf(p, f, 0.05550410f);
    p = fmaf(p, f, 0.24022651f);
    p = fmaf(p, f, 0.69314718f);
    p = fmaf(p, f, 1.0f);
    return p * __int_as_float((nb << 23) + 0x3F800000);
}

// ---------------------------------------------------------------------------
// Pre-round the 4 weight matrices (RNA tf32) into g_wr.
// ---------------------------------------------------------------------------
__global__ void __launch_bounds__(256) round_weights(
    const float* __restrict__ w0, const float* __restrict__ w1,
    const float* __restrict__ w2, const float* __restrict__ w3,
    float* __restrict__ dst)
{
    const int idx = blockIdx.x * 256 + threadIdx.x;   // one float4 each
    const int per = DD * DD / 4;                      // 262144
    const int m = idx / per, off = (idx - m * per) * 4;
    const float* src = (m == 0) ? w0 : (m == 1) ? w1 : (m == 2) ? w2 : w3;
    float4 v = *reinterpret_cast<const float4*>(src + off);
    v.x = rnd_tf(v.x); v.y = rnd_tf(v.y); v.z = rnd_tf(v.z); v.w = rnd_tf(v.w);
    *reinterpret_cast<float4*>(dst + (size_t)m * DD * DD + off) = v;
}

// ---------------------------------------------------------------------------
// GEMM core (unchanged from R16): 128x128 CTA, 8 warps of 32x64,
// 3-stage cp.async, XOR-swizzled pad-free tiles, ldmatrix.x4.
// ---------------------------------------------------------------------------
#define GTILEB 16384                        // one tile: 128 rows * 128 B
#define GSTAGEB (2 * GTILEB)                // A + B per stage = 32768
#define GSMEM_BYTES (3 * GSTAGEB)           // 98304

template <bool IN_HEADS, bool A_CVT>
__device__ __forceinline__ void gemm_core(
    const float* __restrict__ X, const float* __restrict__ W,
    float* sm, int m0, int n0, float c[2][8][4])
{
    const int tid = threadIdx.x;
    const int wid = tid >> 5, lane = tid & 31;
    const int wm0 = (wid >> 1) * 32, wn0 = (wid & 1) * 64;
    const uint32_t smbase = smem_u32(sm);

    auto issue_loads = [&](int k0, int s) {
        const uint32_t As = smbase + (uint32_t)(s * GSTAGEB);
        const uint32_t Bs = As + GTILEB;
        #pragma unroll
        for (int it = 0; it < 4; it++) {
            const int idx = it * 256 + tid;
            const int row = idx >> 3;
            const int c4  = idx & 7;
            const int gk  = k0 + c4 * 4;
            const uint32_t soff = (uint32_t)(row * 128 + ((c4 ^ (row & 7)) << 4));
            const float* pa;
            if (IN_HEADS) {
                const int gm = m0 + row;
                const int bb_ = gm >> 11;
                const int ss_ = gm & (SS - 1);
                pa = X + ((((size_t)bb_ * HH + (gk >> 6)) * SS + ss_) << 6) + (gk & 63);
            } else {
                pa = X + (size_t)(m0 + row) * DD + gk;
            }
            asm volatile("cp.async.cg.shared.global [%0], [%1], 16;"
                         :: "r"(As + soff), "l"(pa));
            const float* pb = W + (size_t)(n0 + row) * DD + gk;
            asm volatile("cp.async.cg.shared.global [%0], [%1], 16;"
                         :: "r"(Bs + soff), "l"(pb));
        }
        asm volatile("cp.async.commit_group;" ::: "memory");
    };

    const int mx = lane >> 3, r8 = lane & 7;
    const uint32_t arow = (uint32_t)((wm0 + ((mx & 1) << 3) + r8) * 128);
    const uint32_t brow = (uint32_t)((wn0 + ((mx >> 1) << 3) + r8) * 128);
    const int cbA = mx >> 1;
    const int cbB = mx & 1;

    auto compute = [&](int s) {
        const uint32_t As = smbase + (uint32_t)(s * GSTAGEB);
        const uint32_t Bs = As + GTILEB;
        #pragma unroll
        for (int ks = 0; ks < 4; ks++) {
            const uint32_t achk = (uint32_t)((((ks * 2 + cbA) ^ r8) << 4));
            const uint32_t bchk = (uint32_t)((((ks * 2 + cbB) ^ r8) << 4));
            uint32_t a[2][4], b[8][2];
            #pragma unroll
            for (int i = 0; i < 2; i++) {
                ldsm4(a[i][0], a[i][1], a[i][2], a[i][3],
                      As + arow + (uint32_t)(i * 2048) + achk);
                if (A_CVT) {
                    a[i][0] = f2tf(__uint_as_float(a[i][0]));
                    a[i][1] = f2tf(__uint_as_float(a[i][1]));
                    a[i][2] = f2tf(__uint_as_float(a[i][2]));
                    a[i][3] = f2tf(__uint_as_float(a[i][3]));
                }
            }
            #pragma unroll
            for (int jp = 0; jp < 4; jp++) {
                ldsm4(b[2 * jp][0], b[2 * jp][1], b[2 * jp + 1][0], b[2 * jp + 1][1],
                      Bs + brow + (uint32_t)(jp * 2048) + bchk);
            }
            #pragma unroll
            for (int i = 0; i < 2; i++)
                #pragma unroll
                for (int j = 0; j < 8; j++)
                    mma8(c[i][j], a[i], b[j][0], b[j][1]);
        }
    };

    auto proc = [&](int ck, int s, bool last) {
        if (last) {
            asm volatile("cp.async.wait_group 0;" ::: "memory");
        } else {
            asm volatile("cp.async.wait_group 1;" ::: "memory");
        }
        __syncthreads();
        if (ck + 2 < 32) issue_loads((ck + 2) * 32, (s + 2) % 3);
        compute(s);
    };

    issue_loads(0, 0);
    issue_loads(32, 1);
    for (int cb = 0; cb < 30; cb += 3) {
        proc(cb + 0, 0, false);
        proc(cb + 1, 1, false);
        proc(cb + 2, 2, false);
    }
    proc(30, 0, false);
    proc(31, 1, true);
    __syncthreads();
}

// ---------------------------------------------------------------------------
// Fused Q/K/V projection GEMM: grid.z selects {0:Q, 1:K, 2:V}.
// ---------------------------------------------------------------------------
__global__ void __launch_bounds__(256, 2) gemm_qkv(
    const float* __restrict__ xq, const float* __restrict__ xk,
    const float* __restrict__ xv, const float* __restrict__ wr,
    const float* __restrict__ bq, const float* __restrict__ bk,
    const float* __restrict__ bv,
    float* __restrict__ yq, float* __restrict__ yk, float* __restrict__ yv,
    float* __restrict__ ktp, float* __restrict__ vtp)
{
    extern __shared__ float sm[];
    const int z = blockIdx.z;
    const int m0 = blockIdx.y * 128, n0 = blockIdx.x * 128;
    const float* X = (z == 0) ? xq : (z == 1) ? xk : xv;
    const float* W = wr + (size_t)z * DD * DD;
    const float* bias = (z == 0) ? bq : (z == 1) ? bk : bv;
    float* Y = (z == 0) ? yq : (z == 1) ? yk : yv;

    float c[2][8][4];
    #pragma unroll
    for (int i = 0; i < 2; i++)
        #pragma unroll
        for (int j = 0; j < 8; j++)
            #pragma unroll
            for (int r = 0; r < 4; r++) c[i][j][r] = 0.f;

    gemm_core<false, true>(X, W, sm, m0, n0, c);

    const int tid = threadIdx.x;
    const int wid = tid >> 5, lane = tid & 31;
    const int g = lane >> 2, t = lane & 3;
    const int wm0 = (wid >> 1) * 32, wn0 = (wid & 1) * 64;

    const int px = kperm(2 * t);
    const int py = kperm(2 * t + 1);
    const int pg = kperm(g);

    #pragma unroll
    for (int i = 0; i < 2; i++) {
        const int r0 = m0 + wm0 + 16 * i + g;
        const int r1 = r0 + 8;
        #pragma unroll
        for (int j = 0; j < 8; j++) {
            const int gn = n0 + wn0 + 8 * j + 2 * t;
            const float bx = __ldg(bias + gn);
            const float by = __ldg(bias + gn + 1);
            float2 o0 = make_float2(c[i][j][0] + bx, c[i][j][1] + by);
            float2 o1 = make_float2(c[i][j][2] + bx, c[i][j][3] + by);
            const int hb = gn >> 6, hc = gn & 63;
            const int b0_ = r0 >> 11, s0_ = r0 & (SS - 1);
            const int b1_ = r1 >> 11, s1_ = r1 & (SS - 1);
            const size_t y0 = ((((size_t)b0_ * HH + hb) * SS + s0_) << 6) + hc;
            const size_t y1 = ((((size_t)b1_ * HH + hb) * SS + s1_) << 6) + hc;
            *reinterpret_cast<float2*>(Y + y0) = o0;
            *reinterpret_cast<float2*>(Y + y1) = o1;
            if (z == 1) {
                const size_t base0 = y0 - (hc & 7);   // hc&7 == 2t
                const size_t base1 = y1 - (hc & 7);
                ktp[base0 + px] = rnd_tf(o0.x);
                ktp[base0 + py] = rnd_tf(o0.y);
                ktp[base1 + px] = rnd_tf(o1.x);
                ktp[base1 + py] = rnd_tf(o1.y);
            } else if (z == 2) {
                const int s0p = (s0_ & ~7) | pg;
                const int s1p = (s1_ & ~7) | pg;
                float* yt0 = vtp + (((size_t)b0_ * HH + hb) * HDIM + hc) * SS + s0p;
                float* yt1 = vtp + (((size_t)b1_ * HH + hb) * HDIM + hc) * SS + s1p;
                yt0[0] = rnd_tf(o0.x); yt0[SS] = rnd_tf(o0.y);
                yt1[0] = rnd_tf(o1.x); yt1[SS] = rnd_tf(o1.y);
            }
        }
    }
}

// ---------------------------------------------------------------------------
// Output-projection GEMM: head-layout in (pre-rounded), flat out.
// ---------------------------------------------------------------------------
__global__ void __launch_bounds__(256, 2) gemm_out(
    const float* __restrict__ X, const float* __restrict__ W,
    const float* __restrict__ bias, float* __restrict__ Y)
{
    extern __shared__ float sm[];
    const int m0 = blockIdx.y * 128, n0 = blockIdx.x * 128;

    float c[2][8][4];
    #pragma unroll
    for (int i = 0; i < 2; i++)
        #pragma unroll
        for (int j = 0; j < 8; j++)
            #pragma unroll
            for (int r = 0; r < 4; r++) c[i][j][r] = 0.f;

    gemm_core<true, false>(X, W, sm, m0, n0, c);

    const int tid = threadIdx.x;
    const int wid = tid >> 5, lane = tid & 31;
    const int g = lane >> 2, t = lane & 3;
    const int wm0 = (wid >> 1) * 32, wn0 = (wid & 1) * 64;

    #pragma unroll
    for (int i = 0; i < 2; i++) {
        const int r0 = m0 + wm0 + 16 * i + g;
        const int r1 = r0 + 8;
        #pragma unroll
        for (int j = 0; j < 8; j++) {
            const int gn = n0 + wn0 + 8 * j + 2 * t;
            const float bx = __ldg(bias + gn);
            const float by = __ldg(bias + gn + 1);
            *reinterpret_cast<float2*>(Y + (size_t)r0 * DD + gn) =
                make_float2(c[i][j][0] + bx, c[i][j][1] + by);
            *reinterpret_cast<float2*>(Y + (size_t)r1 * DD + gn) =
                make_float2(c[i][j][2] + bx, c[i][j][3] + by);
        }
    }
}

// ---------------------------------------------------------------------------
// Tensor-core causal flash attention v4.
// Warp = 32 q-rows (two m16 blocks sharing K/V b-frags); CTA = 128 q-rows.
// Grid (16, H, B). K/V double-buffered cp.async; P via quad shuffles.
// ---------------------------------------------------------------------------
#define KVPAD 72
#define KVTILE (64 * KVPAD)
#define FSMEM_BYTES (4 * KVTILE * 4)   // 73728

__global__ void __launch_bounds__(128, 2) flash_tc(
    const float* __restrict__ qh, const float* __restrict__ kt,
    const float* __restrict__ vt, float* __restrict__ oh)
{
    extern __shared__ float fsm[];
    float* Kb = fsm;                    // [2][64][KVPAD] K[key][d_perm]
    float* Vb = fsm + 2 * KVTILE;       // [2][64][KVPAD] V^T[d][key_perm]

    const int tid = threadIdx.x;
    const int w = tid >> 5, lane = tid & 31;
    const int g = lane >> 2, t = lane & 3;
    const int qi = 15 - (int)blockIdx.x;      // biggest blocks first
    const int h = blockIdx.y, b = blockIdx.z;
    const size_t hoff = ((size_t)b * HH + h) * SS * HDIM;
    const float* vtb = vt + ((size_t)b * HH + h) * HDIM * SS;
    const int q0 = qi * 128;
    const float CLOG = 0.18033688011112042f;  // 0.125 * log2(e)

    const int sr = tid >> 4;            // staging base row (0..7), step 8
    const int sc = (tid & 15) * 4;      // 16B column group

    auto issue_tile = [&](int jt, int buf) {
        float* kd = Kb + buf * KVTILE;
        float* vd = Vb + buf * KVTILE;
        const int kb = jt * 64;
        #pragma unroll
        for (int i = 0; i < 8; i++) {
            const int r = sr + i * 8;
            const float* ks = kt + hoff + (size_t)(kb + r) * HDIM + sc;
            const float* vs = vtb + (size_t)r * SS + kb + sc;
            asm volatile("cp.async.cg.shared.global [%0], [%1], 16;"
                         :: "r"(smem_u32(kd + r * KVPAD + sc)), "l"(ks));
            asm volatile("cp.async.cg.shared.global [%0], [%1], 16;"
                         :: "r"(smem_u32(vd + r * KVPAD + sc)), "l"(vs));
        }
        asm volatile("cp.async.commit_group;" ::: "memory");
    };

    issue_tile(0, 0);   // prefetch tile 0 immediately

    // Row bases: block 0 = base, block 1 = base + 16.
    const int base = q0 + w * 32 + g;
    const int rA0 = base,      rA1 = base + 8;    // block 0 rows (c0/c1, c2/c3)
    const int rB0 = base + 16, rB1 = base + 24;   // block 1 rows

    // ---- Q a-frags straight from gmem (single RNA tf32), both blocks ----
    uint32_t qf[2][8][4];
    {
        const float* pA0 = qh + hoff + (size_t)rA0 * HDIM;
        const float* pA1 = qh + hoff + (size_t)rA1 * HDIM;
        const float* pB0 = qh + hoff + (size_t)rB0 * HDIM;
        const float* pB1 = qh + hoff + (size_t)rB1 * HDIM;
        #pragma unroll
        for (int ks = 0; ks < 8; ks++) {
            qf[0][ks][0] = f2tf(pA0[8 * ks + t]);
            qf[0][ks][1] = f2tf(pA1[8 * ks + t]);
            qf[0][ks][2] = f2tf(pA0[8 * ks + t + 4]);
            qf[0][ks][3] = f2tf(pA1[8 * ks + t + 4]);
            qf[1][ks][0] = f2tf(pB0[8 * ks + t]);
            qf[1][ks][1] = f2tf(pB1[8 * ks + t]);
            qf[1][ks][2] = f2tf(pB0[8 * ks + t + 4]);
            qf[1][ks][3] = f2tf(pB1[8 * ks + t + 4]);
        }
    }

    float o[2][8][4];
    #pragma unroll
    for (int bk_ = 0; bk_ < 2; bk_++)
        #pragma unroll
        for (int nt = 0; nt < 8; nt++)
            #pragma unroll
            for (int r = 0; r < 4; r++) o[bk_][nt][r] = 0.f;
    float mxA0 = -1e30f, mxA1 = -1e30f, lA0 = 0.f, lA1 = 0.f;
    float mxB0 = -1e30f, mxB1 = -1e30f, lB0 = 0.f, lB1 = 0.f;

    const int srcA = 4 * g + (t >> 1);  // P-exchange source lanes (quad)
    const int srcB = srcA + 2;
    const bool c1 = (t & 1);
    const int NT = 2 * qi + 2;          // key tiles covering q0+127

    for (int jt = 0; jt < NT; jt++) {
        const int kb = jt * 64;
        const int buf = jt & 1;

        if (jt < NT - 1) {
            issue_tile(jt + 1, buf ^ 1);
            asm volatile("cp.async.wait_group 1;" ::: "memory");
        } else {
            asm volatile("cp.async.wait_group 0;" ::: "memory");
        }
        __syncthreads();

        const uint32_t* Kt = reinterpret_cast<const uint32_t*>(Kb + buf * KVTILE);
        const uint32_t* VT = reinterpret_cast<const uint32_t*>(Vb + buf * KVTILE);

        // ---- scores: both blocks share each K b-frag ----
        float s[2][8][4];
        #pragma unroll
        for (int nt = 0; nt < 8; nt++) {
            s[0][nt][0] = s[0][nt][1] = s[0][nt][2] = s[0][nt][3] = 0.f;
            s[1][nt][0] = s[1][nt][1] = s[1][nt][2] = s[1][nt][3] = 0.f;
            const uint32_t* kr = Kt + (8 * nt + g) * KVPAD;
            #pragma unroll
            for (int ks = 0; ks < 8; ks++) {
                const uint2 kb2 = *reinterpret_cast<const uint2*>(kr + 8 * ks + 2 * t);
                mma8(s[0][nt], qf[0][ks], kb2.x, kb2.y);
                mma8(s[1][nt], qf[1][ks], kb2.x, kb2.y);
            }
        }

        // ---- causal mask (last two tiles carry the diagonal band) ----
        if (jt >= NT - 2) {
            #pragma unroll
            for (int nt = 0; nt < 8; nt++) {
                const int col = kb + 8 * nt + 2 * t;
                if (col > rA0)     s[0][nt][0] = -1e30f;
                if (col + 1 > rA0) s[0][nt][1] = -1e30f;
                if (col > rA1)     s[0][nt][2] = -1e30f;
                if (col + 1 > rA1) s[0][nt][3] = -1e30f;
                if (col > rB0)     s[1][nt][0] = -1e30f;
                if (col + 1 > rB0) s[1][nt][1] = -1e30f;
                if (col > rB1)     s[1][nt][2] = -1e30f;
                if (col + 1 > rB1) s[1][nt][3] = -1e30f;
            }
        }

        // ---- online softmax, block 0 ----
        {
            float sm0 = -1e30f, sm1 = -1e30f;
            #pragma unroll
            for (int nt = 0; nt < 8; nt++) {
                sm0 = fmaxf(sm0, fmaxf(s[0][nt][0], s[0][nt][1]));
                sm1 = fmaxf(sm1, fmaxf(s[0][nt][2], s[0][nt][3]));
            }
            sm0 = fmaxf(sm0, __shfl_xor_sync(0xffffffffu, sm0, 1));
            sm0 = fmaxf(sm0, __shfl_xor_sync(0xffffffffu, sm0, 2));
            sm1 = fmaxf(sm1, __shfl_xor_sync(0xffffffffu, sm1, 1));
            sm1 = fmaxf(sm1, __shfl_xor_sync(0xffffffffu, sm1, 2));
            const float nm0 = fmaxf(mxA0, sm0), nm1 = fmaxf(mxA1, sm1);
            const float f0 = exp2p((mxA0 - nm0) * CLOG);
            const float f1 = exp2p((mxA1 - nm1) * CLOG);
            mxA0 = nm0; mxA1 = nm1;
            lA0 *= f0; lA1 *= f1;
            #pragma unroll
            for (int nt = 0; nt < 8; nt++) {
                o[0][nt][0] *= f0; o[0][nt][1] *= f0;
                o[0][nt][2] *= f1; o[0][nt][3] *= f1;
            }
            #pragma unroll
            for (int nt = 0; nt < 8; nt++) {
                s[0][nt][0] = exp2p((s[0][nt][0] - mxA0) * CLOG);
                s[0][nt][1] = exp2p((s[0][nt][1] - mxA0) * CLOG);
                s[0][nt][2] = exp2p((s[0][nt][2] - mxA1) * CLOG);
                s[0][nt][3] = exp2p((s[0][nt][3] - mxA1) * CLOG);
                lA0 += s[0][nt][0] + s[0][nt][1];
                lA1 += s[0][nt][2] + s[0][nt][3];
            }
        }
        // ---- online softmax, block 1 ----
        {
            float sm0 = -1e30f, sm1 = -1e30f;
            #pragma unroll
            for (int nt = 0; nt < 8; nt++) {
                sm0 = fmaxf(sm0, fmaxf(s[1][nt][0], s[1][nt][1]));
                sm1 = fmaxf(sm1, fmaxf(s[1][nt][2], s[1][nt][3]));
            }
            sm0 = fmaxf(sm0, __shfl_xor_sync(0xffffffffu, sm0, 1));
            sm0 = fmaxf(sm0, __shfl_xor_sync(0xffffffffu, sm0, 2));
            sm1 = fmaxf(sm1, __shfl_xor_sync(0xffffffffu, sm1, 1));
            sm1 = fmaxf(sm1, __shfl_xor_sync(0xffffffffu, sm1, 2));
            const float nm0 = fmaxf(mxB0, sm0), nm1 = fmaxf(mxB1, sm1);
            const float f0 = exp2p((mxB0 - nm0) * CLOG);
            const float f1 = exp2p((mxB1 - nm1) * CLOG);
            mxB0 = nm0; mxB1 = nm1;
            lB0 *= f0; lB1 *= f1;
            #pragma unroll
            for (int nt = 0; nt < 8; nt++) {
                o[1][nt][0] *= f0; o[1][nt][1] *= f0;
                o[1][nt][2] *= f1; o[1][nt][3] *= f1;
            }
            #pragma unroll
            for (int nt = 0; nt < 8; nt++) {
                s[1][nt][0] = exp2p((s[1][nt][0] - mxB0) * CLOG);
                s[1][nt][1] = exp2p((s[1][nt][1] - mxB0) * CLOG);
                s[1][nt][2] = exp2p((s[1][nt][2] - mxB1) * CLOG);
                s[1][nt][3] = exp2p((s[1][nt][3] - mxB1) * CLOG);
                lB0 += s[1][nt][0] + s[1][nt][1];
                lB1 += s[1][nt][2] + s[1][nt][3];
            }
        }

        // ---- O += P V : both blocks share each V b-frag ----
        #pragma unroll
        for (int kk = 0; kk < 8; kk++) {
            uint32_t ap0[4], ap1[4];
            {
                const float x0 = __shfl_sync(0xffffffffu, s[0][kk][0], srcA);
                const float x1 = __shfl_sync(0xffffffffu, s[0][kk][1], srcA);
                const float y0 = __shfl_sync(0xffffffffu, s[0][kk][2], srcA);
                const float y1 = __shfl_sync(0xffffffffu, s[0][kk][3], srcA);
                const float z0 = __shfl_sync(0xffffffffu, s[0][kk][0], srcB);
                const float z1 = __shfl_sync(0xffffffffu, s[0][kk][1], srcB);
                const float u0 = __shfl_sync(0xffffffffu, s[0][kk][2], srcB);
                const float u1 = __shfl_sync(0xffffffffu, s[0][kk][3], srcB);
                ap0[0] = f2tf(c1 ? x1 : x0);
                ap0[1] = f2tf(c1 ? y1 : y0);
                ap0[2] = f2tf(c1 ? z1 : z0);
                ap0[3] = f2tf(c1 ? u1 : u0);
            }
            {
                const float x0 = __shfl_sync(0xffffffffu, s[1][kk][0], srcA);
                const float x1 = __shfl_sync(0xffffffffu, s[1][kk][1], srcA);
                const float y0 = __shfl_sync(0xffffffffu, s[1][kk][2], srcA);
                const float y1 = __shfl_sync(0xffffffffu, s[1][kk][3], srcA);
                const float z0 = __shfl_sync(0xffffffffu, s[1][kk][0], srcB);
                const float z1 = __shfl_sync(0xffffffffu, s[1][kk][1], srcB);
                const float u0 = __shfl_sync(0xffffffffu, s[1][kk][2], srcB);
                const float u1 = __shfl_sync(0xffffffffu, s[1][kk][3], srcB);
                ap1[0] = f2tf(c1 ? x1 : x0);
                ap1[1] = f2tf(c1 ? y1 : y0);
                ap1[2] = f2tf(c1 ? z1 : z0);
                ap1[3] = f2tf(c1 ? u1 : u0);
            }
            #pragma unroll
            for (int nt = 0; nt < 8; nt++) {
                const uint32_t* vr = VT + (8 * nt + g) * KVPAD;
                const uint2 vv = *reinterpret_cast<const uint2*>(vr + 8 * kk + 2 * t);
                mma8(o[0][nt], ap0, vv.x, vv.y);
                mma8(o[1][nt], ap1, vv.x, vv.y);
            }
        }
        __syncthreads();   // all warps done reading this buffer before reuse
    }

    // ---- finalize (write RNA-pre-rounded for the output-proj GEMM) ----
    lA0 += __shfl_xor_sync(0xffffffffu, lA0, 1);
    lA0 += __shfl_xor_sync(0xffffffffu, lA0, 2);
    lA1 += __shfl_xor_sync(0xffffffffu, lA1, 1);
    lA1 += __shfl_xor_sync(0xffffffffu, lA1, 2);
    lB0 += __shfl_xor_sync(0xffffffffu, lB0, 1);
    lB0 += __shfl_xor_sync(0xffffffffu, lB0, 2);
    lB1 += __shfl_xor_sync(0xffffffffu, lB1, 1);
    lB1 += __shfl_xor_sync(0xffffffffu, lB1, 2);
    const float iA0 = 1.f / lA0, iA1 = 1.f / lA1;
    const float iB0 = 1.f / lB0, iB1 = 1.f / lB1;

    float* pA0 = oh + hoff + (size_t)rA0 * HDIM;
    float* pA1 = oh + hoff + (size_t)rA1 * HDIM;
    float* pB0 = oh + hoff + (size_t)rB0 * HDIM;
    float* pB1 = oh + hoff + (size_t)rB1 * HDIM;
    #pragma unroll
    for (int nt = 0; nt < 8; nt++) {
        const int d = 8 * nt + 2 * t;
        *reinterpret_cast<float2*>(pA0 + d) =
            make_float2(rnd_tf(o[0][nt][0] * iA0), rnd_tf(o[0][nt][1] * iA0));
        *reinterpret_cast<float2*>(pA1 + d) =
            make_float2(rnd_tf(o[0][nt][2] * iA1), rnd_tf(o[0][nt][3] * iA1));
        *reinterpret_cast<float2*>(pB0 + d) =
            make_float2(rnd_tf(o[1][nt][0] * iB0), rnd_tf(o[1][nt][1] * iB0));
        *reinterpret_cast<float2*>(pB1 + d) =
            make_float2(rnd_tf(o[1][nt][2] * iB1), rnd_tf(o[1][nt][3] * iB1));
    }
}

// ---------------------------------------------------------------------------
// kernel_launch
// Inputs: 0=q 1=k 2=v 3=mask 4=Wq 5=bq 6=Wk 7=bk 8=Wv 9=bv 10=Wo 11=bo
// Output: [out (B,S,D)] [kh (B,H,S,HD)] [vh (B,H,S,HD)]
// ---------------------------------------------------------------------------
extern "C" void kernel_launch(void* const* d_in, const int* in_sizes, int n_in,
                              void* d_out, int out_size)
{
    const float* q  = (const float*)d_in[0];
    const float* k  = (const float*)d_in[1];
    const float* v  = (const float*)d_in[2];
    const float* Wq = (const float*)d_in[4];
    const float* bq = (const float*)d_in[5];
    const float* Wk = (const float*)d_in[6];
    const float* bk = (const float*)d_in[7];
    const float* Wv = (const float*)d_in[8];
    const float* bv = (const float*)d_in[9];
    const float* Wo = (const float*)d_in[10];
    const float* bo = (const float*)d_in[11];

    float* out = (float*)d_out;
    float* khp = out + HEADTOT;
    float* vhp = khp + HEADTOT;

    float *qh_p = nullptr, *att_p = nullptr, *kt_p = nullptr, *vt_p = nullptr, *wr_p = nullptr;
    cudaGetSymbolAddress((void**)&qh_p, g_qh);
    cudaGetSymbolAddress((void**)&att_p, g_att);
    cudaGetSymbolAddress((void**)&kt_p, g_kt);
    cudaGetSymbolAddress((void**)&vt_p, g_vt);
    cudaGetSymbolAddress((void**)&wr_p, g_wr);

    cudaFuncSetAttribute(gemm_qkv,
                         cudaFuncAttributeMaxDynamicSharedMemorySize, GSMEM_BYTES);
    cudaFuncSetAttribute(gemm_out,
                         cudaFuncAttributeMaxDynamicSharedMemorySize, GSMEM_BYTES);
    cudaFuncSetAttribute(flash_tc,
                         cudaFuncAttributeMaxDynamicSharedMemorySize, FSMEM_BYTES);

    // Pre-round all 4 weight matrices (RNA tf32) -> g_wr
    round_weights<<<4096, 256>>>(Wq, Wk, Wv, Wo, wr_p);

    // Fused Q/K/V projections: grid (8, 64, 3)
    gemm_qkv<<<dim3(DD / 128, MTOT / 128, 3), 256, GSMEM_BYTES>>>(
        q, k, v, wr_p, bq, bk, bv, qh_p, khp, vhp, kt_p, vt_p);

    flash_tc<<<dim3(16, HH, BB), 128, FSMEM_BYTES>>>(qh_p, kt_p, vt_p, att_p);

    gemm_out<<<dim3(DD / 128, MTOT / 128), 256, GSMEM_BYTES>>>(
        att_p, wr_p + 3 * DD * DD, bo, out);
}